// round 6
// baseline (speedup 1.0000x reference)
#include <cuda_runtime.h>
#include <cuda_bf16.h>
#include <cstdint>

#define NN 50000
#define EE 800000
#define FIN 128
#define HID 100
#define CL 16
#define LEAKYS 0.01f
#define NB_SCAN 196   // ceil(NN/256)

// Scratch (alloc-free rule: __device__ globals). All fully rewritten each call.
__device__ int   g_cnt[NN];
__device__ int   g_off[NN];
__device__ int   g_cur[NN];
__device__ int   g_bsum[256];
__device__ float g_dinv[NN];
__device__ int   g_csrc[EE];
__device__ float g_Hs1[NN * HID];  // (x@W1) * dinv[row]
__device__ float g_Hs2[NN * CL];   // (leaky(out1)@W2) * dinv[row]

// ---------------- CSR build ----------------
__global__ void k_zero() {
    int i = blockIdx.x * blockDim.x + threadIdx.x;
    if (i < NN) g_cnt[i] = 0;
}
__global__ void k_hist(const int* __restrict__ ei) {
    int e = blockIdx.x * blockDim.x + threadIdx.x;
    if (e < EE) atomicAdd(&g_cnt[ei[EE + e]], 1);
}
__global__ void k_scanA() {
    __shared__ int s[256];
    int tid = threadIdx.x;
    int i = blockIdx.x * 256 + tid;
    int val = (i < NN) ? g_cnt[i] : 0;
    if (i < NN) g_dinv[i] = rsqrtf((float)val + 1.0f);
    s[tid] = val;
    __syncthreads();
#pragma unroll
    for (int off = 1; off < 256; off <<= 1) {
        int t = (tid >= off) ? s[tid - off] : 0;
        __syncthreads();
        s[tid] += t;
        __syncthreads();
    }
    if (i < NN) g_off[i] = s[tid] - val;
    if (tid == 255) g_bsum[blockIdx.x] = s[255];
}
__global__ void k_scanB() {
    __shared__ int s[256];
    int tid = threadIdx.x;
    int val = (tid < NB_SCAN) ? g_bsum[tid] : 0;
    s[tid] = val;
    __syncthreads();
#pragma unroll
    for (int off = 1; off < 256; off <<= 1) {
        int t = (tid >= off) ? s[tid - off] : 0;
        __syncthreads();
        s[tid] += t;
        __syncthreads();
    }
    g_bsum[tid] = s[tid] - val;
}
__global__ void k_scanC() {
    int i = blockIdx.x * 256 + threadIdx.x;
    if (i < NN) {
        int o = g_off[i] + g_bsum[blockIdx.x];
        g_off[i] = o;
        g_cur[i] = o;
    }
}
__global__ void k_place(const int* __restrict__ ei) {
    int e = blockIdx.x * blockDim.x + threadIdx.x;
    if (e < EE) {
        int d = ei[EE + e];
        int pos = atomicAdd(&g_cur[d], 1);
        g_csrc[pos] = ei[e];
    }
}

// ---------------- GEMM1 via warp MMA (HMMA bf16, 3-term fp32 split) ----------------
// Hs1 = (x @ W1) * dinv[row].  A=x[128 tile][128k] hi/lo bf16; B=W1^T [n][k] hi/lo.
#define LDK 136           // smem row stride in bf16 (conflict-free: 68 words, 68%32=4)
#define SMB_TILE (128 * LDK)          // bf16 elements per tile
#define SMB_BYTES (SMB_TILE * 2)      // 34816 B
#define GEMM1_SMEM (4 * SMB_BYTES)    // 139264 B

__device__ __forceinline__ uint32_t pack_bf16x2(float a, float b) {
    __nv_bfloat162 t = __floats2bfloat162_rn(a, b);  // .x=a (low), .y=b (high)
    return *(uint32_t*)&t;
}

__device__ __forceinline__ void mma_bf16(float& d0, float& d1, float& d2, float& d3,
                                         uint32_t a0, uint32_t a1, uint32_t a2, uint32_t a3,
                                         uint32_t b0, uint32_t b1) {
    asm volatile(
        "mma.sync.aligned.m16n8k16.row.col.f32.bf16.bf16.f32 "
        "{%0,%1,%2,%3}, {%4,%5,%6,%7}, {%8,%9}, {%0,%1,%2,%3};"
        : "+f"(d0), "+f"(d1), "+f"(d2), "+f"(d3)
        : "r"(a0), "r"(a1), "r"(a2), "r"(a3), "r"(b0), "r"(b1));
}

__global__ __launch_bounds__(256, 1) void k_gemm1_mma(const float* __restrict__ x,
                                                      const float* __restrict__ W1) {
    extern __shared__ char smem[];
    uint32_t* sAhi = (uint32_t*)smem;                       // [128][68] u32 view
    uint32_t* sAlo = (uint32_t*)(smem + SMB_BYTES);
    __nv_bfloat16* sBhi16 = (__nv_bfloat16*)(smem + 2 * SMB_BYTES);
    __nv_bfloat16* sBlo16 = (__nv_bfloat16*)(smem + 3 * SMB_BYTES);
    uint32_t* sBhi = (uint32_t*)sBhi16;
    uint32_t* sBlo = (uint32_t*)sBlo16;

    int tid = threadIdx.x;
    int m0 = blockIdx.x * 128;

    // ---- load + convert A: thread t covers row t/2, k-half (t&1)*64 ----
    {
        int rl = tid >> 1;
        int kh = (tid & 1) * 64;
        int row = m0 + rl;
        uint32_t* dsth = sAhi + rl * (LDK / 2) + kh / 2;
        uint32_t* dstl = sAlo + rl * (LDK / 2) + kh / 2;
        if (row < NN) {
            const float4* src = (const float4*)(x + (long)row * FIN + kh);
#pragma unroll
            for (int i = 0; i < 16; i++) {
                float4 v = src[i];
                __nv_bfloat16 h0 = __float2bfloat16(v.x);
                __nv_bfloat16 h1 = __float2bfloat16(v.y);
                __nv_bfloat16 h2 = __float2bfloat16(v.z);
                __nv_bfloat16 h3 = __float2bfloat16(v.w);
                float l0 = v.x - __bfloat162float(h0);
                float l1 = v.y - __bfloat162float(h1);
                float l2 = v.z - __bfloat162float(h2);
                float l3 = v.w - __bfloat162float(h3);
                __nv_bfloat162 hp0; hp0.x = h0; hp0.y = h1;
                __nv_bfloat162 hp1; hp1.x = h2; hp1.y = h3;
                dsth[i * 2 + 0] = *(uint32_t*)&hp0;
                dsth[i * 2 + 1] = *(uint32_t*)&hp1;
                dstl[i * 2 + 0] = pack_bf16x2(l0, l1);
                dstl[i * 2 + 1] = pack_bf16x2(l2, l3);
            }
        } else {
#pragma unroll
            for (int i = 0; i < 32; i++) { dsth[i] = 0u; dstl[i] = 0u; }
        }
    }
    // ---- load + convert B: W1[k][n] -> sB[n][k]; n = tid&127, k-half tid>>7 ----
    {
        int n = tid & 127;
        int k0 = (tid >> 7) * 64;
        bool ok = n < HID;
#pragma unroll 8
        for (int kk = 0; kk < 64; kk++) {
            int k = k0 + kk;
            float v = ok ? W1[k * HID + n] : 0.0f;
            __nv_bfloat16 h = __float2bfloat16(v);
            __nv_bfloat16 l = __float2bfloat16(v - __bfloat162float(h));
            sBhi16[n * LDK + k] = h;
            sBlo16[n * LDK + k] = l;
        }
    }
    __syncthreads();

    // ---- compute: warp (mw 0..3, nw 0..1) owns rows mw*32..+31, cols nw*64..+63 ----
    int wid = tid >> 5, lane = tid & 31;
    int mw = wid & 3, nw = wid >> 2;
    int gid = lane >> 2, tig = lane & 3;

    float acc[2][8][4];
#pragma unroll
    for (int mt = 0; mt < 2; mt++)
#pragma unroll
        for (int nt = 0; nt < 8; nt++)
#pragma unroll
            for (int q = 0; q < 4; q++) acc[mt][nt][q] = 0.0f;

#pragma unroll
    for (int ks = 0; ks < 8; ks++) {
        int kw = ks * 8 + tig;  // u32 index of k-pair (k0 + tig*2)/2
        uint32_t ah[2][4], al[2][4];
#pragma unroll
        for (int mt = 0; mt < 2; mt++) {
            int r0 = (mw * 32 + mt * 16 + gid) * (LDK / 2);
            int r1 = r0 + 8 * (LDK / 2);
            ah[mt][0] = sAhi[r0 + kw];
            ah[mt][1] = sAhi[r1 + kw];
            ah[mt][2] = sAhi[r0 + kw + 4];
            ah[mt][3] = sAhi[r1 + kw + 4];
            al[mt][0] = sAlo[r0 + kw];
            al[mt][1] = sAlo[r1 + kw];
            al[mt][2] = sAlo[r0 + kw + 4];
            al[mt][3] = sAlo[r1 + kw + 4];
        }
#pragma unroll
        for (int nt = 0; nt < 8; nt++) {
            int nb = (nw * 64 + nt * 8 + gid) * (LDK / 2);
            uint32_t bh0 = sBhi[nb + kw];
            uint32_t bh1 = sBhi[nb + kw + 4];
            uint32_t bl0 = sBlo[nb + kw];
            uint32_t bl1 = sBlo[nb + kw + 4];
#pragma unroll
            for (int mt = 0; mt < 2; mt++) {
                float* d = acc[mt][nt];
                mma_bf16(d[0], d[1], d[2], d[3],
                         ah[mt][0], ah[mt][1], ah[mt][2], ah[mt][3], bh0, bh1);
                mma_bf16(d[0], d[1], d[2], d[3],
                         al[mt][0], al[mt][1], al[mt][2], al[mt][3], bh0, bh1);
                mma_bf16(d[0], d[1], d[2], d[3],
                         ah[mt][0], ah[mt][1], ah[mt][2], ah[mt][3], bl0, bl1);
            }
        }
    }

    // ---- epilogue: scale by dinv, write Hs1 (float2, cols even) ----
#pragma unroll
    for (int mt = 0; mt < 2; mt++) {
        int row0 = m0 + mw * 32 + mt * 16 + gid;
        int row1 = row0 + 8;
        float di0 = (row0 < NN) ? g_dinv[row0] : 0.0f;
        float di1 = (row1 < NN) ? g_dinv[row1] : 0.0f;
#pragma unroll
        for (int nt = 0; nt < 8; nt++) {
            int c = nw * 64 + nt * 8 + tig * 2;
            if (c < HID) {
                float* d = acc[mt][nt];
                if (row0 < NN)
                    *(float2*)(g_Hs1 + (long)row0 * HID + c) =
                        make_float2(d[0] * di0, d[1] * di0);
                if (row1 < NN)
                    *(float2*)(g_Hs1 + (long)row1 * HID + c) =
                        make_float2(d[2] * di1, d[3] * di1);
            }
        }
    }
}

// ---------------- Gather layer 1 + leaky + fused GEMM2 ----------------
__global__ __launch_bounds__(256) void k_gather1(const float* __restrict__ b1,
                                                 const float* __restrict__ W2,
                                                 const float* __restrict__ b2,
                                                 float* __restrict__ out) {
    __shared__ float W2s[HID][17];
    __shared__ float b1s[HID];
    __shared__ float b2s[CL];
    __shared__ float us[8][HID];
    int tid = threadIdx.x;
    for (int i = tid; i < HID * CL; i += 256) W2s[i / CL][i % CL] = W2[i];
    for (int i = tid; i < HID; i += 256) b1s[i] = b1[i];
    if (tid < CL) b2s[tid] = b2[tid];
    __syncthreads();

    int wid = tid >> 5, lane = tid & 31;
    int node = blockIdx.x * 8 + wid;
    if (node >= NN) return;

    int c0 = lane, c1 = lane + 32, c2 = lane + 64, c3 = lane + 96;
    bool has3 = c3 < HID;
    const float* selfrow = g_Hs1 + (long)node * HID;
    float a0 = selfrow[c0];
    float a1 = selfrow[c1];
    float a2 = selfrow[c2];
    float a3 = has3 ? selfrow[c3] : 0.0f;

    int start = g_off[node];
    int end = start + g_cnt[node];
    for (int j = start; j < end; j++) {
        int s = g_csrc[j];
        const float* r = g_Hs1 + (long)s * HID;
        a0 += r[c0];
        a1 += r[c1];
        a2 += r[c2];
        if (has3) a3 += r[c3];
    }

    float di = g_dinv[node];
    float o0 = b1s[c0] + di * a0;
    float o1 = b1s[c1] + di * a1;
    float o2 = b1s[c2] + di * a2;
    us[wid][c0] = o0 > 0.f ? o0 : LEAKYS * o0;
    us[wid][c1] = o1 > 0.f ? o1 : LEAKYS * o1;
    us[wid][c2] = o2 > 0.f ? o2 : LEAKYS * o2;
    if (has3) {
        float o3 = b1s[c3] + di * a3;
        us[wid][c3] = o3 > 0.f ? o3 : LEAKYS * o3;
    }
    __syncwarp();

    int c = lane & 15;
    int k0 = (lane >> 4) * 50;
    float p = 0.0f;
#pragma unroll 5
    for (int k = 0; k < 50; k++) {
        p += us[wid][k0 + k] * W2s[k0 + k][c];
    }
    p += __shfl_xor_sync(0xffffffffu, p, 16);
    if (lane < 16) {
        float h2 = di * p;
        g_Hs2[(long)node * CL + c] = h2;
        out[(long)node * CL + c] = b2s[c] + h2 * di;
    }
}

// ---------------- Gather layer 2 + log_softmax ----------------
__global__ __launch_bounds__(256) void k_gather2(float* __restrict__ out) {
    int t = blockIdx.x * 256 + threadIdx.x;
    int node = t >> 4;
    int c = t & 15;
    if (node >= NN) return;

    int start = g_off[node];
    int end = start + g_cnt[node];
    float acc = 0.0f;
    for (int j = start; j < end; j++) {
        int s = g_csrc[j];
        acc += g_Hs2[(long)s * CL + c];
    }
    float v = out[(long)node * CL + c] + g_dinv[node] * acc;

    float m = v;
#pragma unroll
    for (int msk = 8; msk >= 1; msk >>= 1)
        m = fmaxf(m, __shfl_xor_sync(0xffffffffu, m, msk, 16));
    float e = expf(v - m);
#pragma unroll
    for (int msk = 8; msk >= 1; msk >>= 1)
        e += __shfl_xor_sync(0xffffffffu, e, msk, 16);
    out[(long)node * CL + c] = v - m - logf(e);
}

extern "C" void kernel_launch(void* const* d_in, const int* in_sizes, int n_in,
                              void* d_out, int out_size) {
    const float* x  = (const float*)d_in[0];
    const float* W1 = (const float*)d_in[1];
    const float* b1 = (const float*)d_in[2];
    const float* W2 = (const float*)d_in[3];
    const float* b2 = (const float*)d_in[4];
    const int*   ei = (const int*)d_in[5];
    float* out = (float*)d_out;

    cudaFuncSetAttribute(k_gemm1_mma, cudaFuncAttributeMaxDynamicSharedMemorySize,
                         GEMM1_SMEM);

    k_zero<<<NB_SCAN, 256>>>();
    k_hist<<<(EE + 255) / 256, 256>>>(ei);
    k_scanA<<<NB_SCAN, 256>>>();
    k_scanB<<<1, 256>>>();
    k_scanC<<<NB_SCAN, 256>>>();
    k_place<<<(EE + 255) / 256, 256>>>(ei);
    k_gemm1_mma<<<(NN + 127) / 128, 256, GEMM1_SMEM>>>(x, W1);
    k_gather1<<<(NN + 7) / 8, 256>>>(b1, W2, b2, out);
    k_gather2<<<(NN * 16 + 255) / 256, 256>>>(out);
}

// round 7
// speedup vs baseline: 1.3639x; 1.3639x over previous
#include <cuda_runtime.h>
#include <cstdint>

#define NN 50000
#define EE 800000
#define FIN 128
#define HID 100
#define CL 16
#define LEAKYS 0.01f
#define NB_SCAN 196   // ceil(NN/256)

typedef unsigned long long ull;

// Scratch (alloc-free rule: __device__ globals). All fully rewritten each call.
__device__ int   g_cnt[NN];
__device__ int   g_off[NN];
__device__ int   g_cur[NN];
__device__ int   g_bsum[NB_SCAN];
__device__ float g_dinv[NN];
__device__ int   g_csrc[EE];
__device__ float g_Hs1[NN * HID];  // (x@W1) * dinv[row]
__device__ float g_Hs2[NN * CL];   // (leaky(out1)@W2) * dinv[row]

// ---------------- CSR build ----------------
__global__ void k_zero() {
    int i = blockIdx.x * blockDim.x + threadIdx.x;
    if (i < NN) g_cnt[i] = 0;
}
__global__ void k_hist(const int* __restrict__ ei) {
    int e = blockIdx.x * blockDim.x + threadIdx.x;
    if (e < EE) atomicAdd(&g_cnt[ei[EE + e]], 1);
}
// Per-block exclusive scan; also dinv = rsqrt(cnt+1); writes block totals.
__global__ void k_scanA() {
    __shared__ int s[256];
    int tid = threadIdx.x;
    int i = blockIdx.x * 256 + tid;
    int val = (i < NN) ? g_cnt[i] : 0;
    if (i < NN) g_dinv[i] = rsqrtf((float)val + 1.0f);
    s[tid] = val;
    __syncthreads();
#pragma unroll
    for (int off = 1; off < 256; off <<= 1) {
        int t = (tid >= off) ? s[tid - off] : 0;
        __syncthreads();
        s[tid] += t;
        __syncthreads();
    }
    if (i < NN) g_off[i] = s[tid] - val;
    if (tid == 255) g_bsum[blockIdx.x] = s[255];
}
// Fused: each block reduces bsum[0..bid-1] itself, then finalizes offsets.
__global__ void k_scanC() {
    __shared__ int red[256];
    int tid = threadIdx.x;
    int bid = blockIdx.x;
    int v = (tid < bid) ? g_bsum[tid] : 0;   // NB_SCAN <= 256
    red[tid] = v;
    __syncthreads();
#pragma unroll
    for (int off = 128; off >= 1; off >>= 1) {
        if (tid < off) red[tid] += red[tid + off];
        __syncthreads();
    }
    int base = red[0];
    int i = bid * 256 + tid;
    if (i < NN) {
        int o = g_off[i] + base;
        g_off[i] = o;
        g_cur[i] = o;
    }
}
__global__ void k_place(const int* __restrict__ ei) {
    int e = blockIdx.x * blockDim.x + threadIdx.x;
    if (e < EE) {
        int d = ei[EE + e];
        int pos = atomicAdd(&g_cur[d], 1);
        g_csrc[pos] = ei[e];
    }
}

// ---------------- GEMM1 (SIMT, packed f32x2 FMA) ----------------
// Hs1 = (x @ W1) * dinv[row]. BM=128, BN=128(pad), BK=16, 256 thr, 8x8/thread.
// Accumulators are 32 packed f32x2 pairs -> fma.rn.f32x2 (2 FMA/issue).
__device__ __forceinline__ void fma2(ull& d, ull a, ull b) {
    asm("fma.rn.f32x2 %0, %1, %2, %0;" : "+l"(d) : "l"(a), "l"(b));
}
__device__ __forceinline__ ull packdup(float a) {
    ull r;
    asm("mov.b64 %0, {%1, %1};" : "=l"(r) : "f"(a));
    return r;
}

__global__ __launch_bounds__(256) void k_gemm1(const float* __restrict__ x,
                                               const float* __restrict__ W1) {
    __shared__ float As[2][16][128];  // [buf][k][m]
    __shared__ float Bs[2][16][128];  // [buf][k][n]
    int tid = threadIdx.x;
    int tx = tid & 15, ty = tid >> 4;
    int m0 = blockIdx.x * 128;

    int mA = tid >> 1;
    int kA = (tid & 1) * 8;
    int rowA = m0 + mA;
    bool okA = rowA < NN;
    const float* xrow = x + (long)rowA * FIN + kA;

    float4 rA0, rA1;
    float rB[8];
    {
        rA0 = okA ? *(const float4*)(xrow + 0) : make_float4(0, 0, 0, 0);
        rA1 = okA ? *(const float4*)(xrow + 4) : make_float4(0, 0, 0, 0);
#pragma unroll
        for (int i = 0; i < 8; i++) {
            int idx = tid + i * 256;
            int k = idx >> 7, n = idx & 127;
            rB[i] = (n < HID) ? W1[k * HID + n] : 0.0f;
        }
        float av[8] = {rA0.x, rA0.y, rA0.z, rA0.w, rA1.x, rA1.y, rA1.z, rA1.w};
#pragma unroll
        for (int j = 0; j < 8; j++) As[0][kA + j][mA] = av[j];
#pragma unroll
        for (int i = 0; i < 8; i++) {
            int idx = tid + i * 256;
            Bs[0][idx >> 7][idx & 127] = rB[i];
        }
    }
    __syncthreads();

    ull acc[8][4];  // [mi][nj-pair]; f32x2 zero == 0ull
#pragma unroll
    for (int i = 0; i < 8; i++)
#pragma unroll
        for (int j = 0; j < 4; j++) acc[i][j] = 0ull;

    for (int t = 0; t < 8; t++) {
        int buf = t & 1;
        if (t < 7) {
            int kk = (t + 1) * 16;
            rA0 = okA ? *(const float4*)(xrow + kk + 0) : make_float4(0, 0, 0, 0);
            rA1 = okA ? *(const float4*)(xrow + kk + 4) : make_float4(0, 0, 0, 0);
#pragma unroll
            for (int i = 0; i < 8; i++) {
                int idx = tid + i * 256;
                int k = idx >> 7, n = idx & 127;
                rB[i] = (n < HID) ? W1[(kk + k) * HID + n] : 0.0f;
            }
        }
#pragma unroll
        for (int k = 0; k < 16; k++) {
            float4 a0 = *(const float4*)&As[buf][k][ty * 8];
            float4 a1 = *(const float4*)&As[buf][k][ty * 8 + 4];
            const ull* bp = (const ull*)&Bs[buf][k][tx * 8];
            ull b2[4] = {bp[0], bp[1], bp[2], bp[3]};
            float a[8] = {a0.x, a0.y, a0.z, a0.w, a1.x, a1.y, a1.z, a1.w};
#pragma unroll
            for (int i = 0; i < 8; i++) {
                ull a2 = packdup(a[i]);
#pragma unroll
                for (int j = 0; j < 4; j++) fma2(acc[i][j], a2, b2[j]);
            }
        }
        if (t < 7) {
            int nb = buf ^ 1;
            float av[8] = {rA0.x, rA0.y, rA0.z, rA0.w, rA1.x, rA1.y, rA1.z, rA1.w};
#pragma unroll
            for (int j = 0; j < 8; j++) As[nb][kA + j][mA] = av[j];
#pragma unroll
            for (int i = 0; i < 8; i++) {
                int idx = tid + i * 256;
                Bs[nb][idx >> 7][idx & 127] = rB[i];
            }
            __syncthreads();
        }
    }

#pragma unroll
    for (int i = 0; i < 8; i++) {
        int row = m0 + ty * 8 + i;
        if (row >= NN) continue;
        float di = g_dinv[row];
#pragma unroll
        for (int j = 0; j < 4; j++) {
            int col = tx * 8 + j * 2;
            if (col < HID) {
                float lo, hi;
                asm("mov.b64 {%0, %1}, %2;" : "=f"(lo), "=f"(hi) : "l"(acc[i][j]));
                *(float2*)(g_Hs1 + (long)row * HID + col) =
                    make_float2(lo * di, hi * di);
            }
        }
    }
}

// ---------------- Gather layer 1 + leaky + fused GEMM2 ----------------
__global__ __launch_bounds__(256) void k_gather1(const float* __restrict__ b1,
                                                 const float* __restrict__ W2,
                                                 const float* __restrict__ b2,
                                                 float* __restrict__ out) {
    __shared__ float W2s[HID][17];
    __shared__ float b1s[HID];
    __shared__ float b2s[CL];
    __shared__ float us[8][HID];
    int tid = threadIdx.x;
    for (int i = tid; i < HID * CL; i += 256) W2s[i / CL][i % CL] = W2[i];
    for (int i = tid; i < HID; i += 256) b1s[i] = b1[i];
    if (tid < CL) b2s[tid] = b2[tid];
    __syncthreads();

    int wid = tid >> 5, lane = tid & 31;
    int node = blockIdx.x * 8 + wid;
    if (node >= NN) return;

    int c0 = lane, c1 = lane + 32, c2 = lane + 64, c3 = lane + 96;
    bool has3 = c3 < HID;
    const float* selfrow = g_Hs1 + (long)node * HID;
    float a0 = selfrow[c0];
    float a1 = selfrow[c1];
    float a2 = selfrow[c2];
    float a3 = has3 ? selfrow[c3] : 0.0f;

    int start = g_off[node];
    int end = start + g_cnt[node];
    for (int j = start; j < end; j++) {
        int s = g_csrc[j];
        const float* r = g_Hs1 + (long)s * HID;
        a0 += r[c0];
        a1 += r[c1];
        a2 += r[c2];
        if (has3) a3 += r[c3];
    }

    float di = g_dinv[node];
    float o0 = b1s[c0] + di * a0;
    float o1 = b1s[c1] + di * a1;
    float o2 = b1s[c2] + di * a2;
    us[wid][c0] = o0 > 0.f ? o0 : LEAKYS * o0;
    us[wid][c1] = o1 > 0.f ? o1 : LEAKYS * o1;
    us[wid][c2] = o2 > 0.f ? o2 : LEAKYS * o2;
    if (has3) {
        float o3 = b1s[c3] + di * a3;
        us[wid][c3] = o3 > 0.f ? o3 : LEAKYS * o3;
    }
    __syncwarp();

    int c = lane & 15;
    int k0 = (lane >> 4) * 50;
    float p = 0.0f;
#pragma unroll 5
    for (int k = 0; k < 50; k++) {
        p += us[wid][k0 + k] * W2s[k0 + k][c];
    }
    p += __shfl_xor_sync(0xffffffffu, p, 16);
    if (lane < 16) {
        float h2 = di * p;
        g_Hs2[(long)node * CL + c] = h2;
        out[(long)node * CL + c] = b2s[c] + h2 * di;
    }
}

// ---------------- Gather layer 2 + log_softmax ----------------
__global__ __launch_bounds__(256) void k_gather2(float* __restrict__ out) {
    int t = blockIdx.x * 256 + threadIdx.x;
    int node = t >> 4;
    int c = t & 15;
    if (node >= NN) return;

    int start = g_off[node];
    int end = start + g_cnt[node];
    float acc = 0.0f;
    for (int j = start; j < end; j++) {
        int s = g_csrc[j];
        acc += g_Hs2[(long)s * CL + c];
    }
    float v = out[(long)node * CL + c] + g_dinv[node] * acc;

    float m = v;
#pragma unroll
    for (int msk = 8; msk >= 1; msk >>= 1)
        m = fmaxf(m, __shfl_xor_sync(0xffffffffu, m, msk, 16));
    float e = expf(v - m);
#pragma unroll
    for (int msk = 8; msk >= 1; msk >>= 1)
        e += __shfl_xor_sync(0xffffffffu, e, msk, 16);
    out[(long)node * CL + c] = v - m - logf(e);
}

extern "C" void kernel_launch(void* const* d_in, const int* in_sizes, int n_in,
                              void* d_out, int out_size) {
    const float* x  = (const float*)d_in[0];
    const float* W1 = (const float*)d_in[1];
    const float* b1 = (const float*)d_in[2];
    const float* W2 = (const float*)d_in[3];
    const float* b2 = (const float*)d_in[4];
    const int*   ei = (const int*)d_in[5];
    float* out = (float*)d_out;

    k_zero<<<NB_SCAN, 256>>>();
    k_hist<<<(EE + 255) / 256, 256>>>(ei);
    k_scanA<<<NB_SCAN, 256>>>();
    k_scanC<<<NB_SCAN, 256>>>();
    k_place<<<(EE + 255) / 256, 256>>>(ei);
    k_gemm1<<<(NN + 127) / 128, 256>>>(x, W1);
    k_gather1<<<(NN + 7) / 8, 256>>>(b1, W2, b2, out);
    k_gather2<<<(NN * 16 + 255) / 256, 256>>>(out);
}